// round 9
// baseline (speedup 1.0000x reference)
#include <cuda_runtime.h>
#include <cuda_bf16.h>
#include <cstdint>

// Problem constants
#define VCODES 8192
#define DDIM   256
#define MROWS  32768      // 8 * 16*16*16
#define SPAT   4096       // 16*16*16

// Output layout (concatenated f32)
#define O_QUANT 0ul
#define O_IDX   8388608ul
#define O_QD    8421376ul
#define O_NEWN  8421377ul
#define O_ZAVG  8429569ul
#define O_NEWW  10526721ul

#define MARGIN 6.0f

// ---------------------------------------------------------------------------
// Scratch (device globals; no allocations allowed)
__device__ unsigned long long g_best[MROWS];
__device__ int   g_idx[MROWS];
__device__ float g_counts[VCODES];
__device__ float g_encsum[VCODES * DDIM];
__device__ float g_wsq[VCODES];
__device__ float g_sx[MROWS];                    // per-row int8 scale (x)
__device__ float g_sw[VCODES];                   // per-code int8 scale (w)
__device__ float g_sumN;
__device__ float g_qd;
__device__ uint8_t g_axs8[MROWS * DDIM];         // flat x, int8
__device__ uint8_t g_wxs8[VCODES * DDIM];        // weight, int8
__device__ __nv_bfloat16 g_scores[(size_t)MROWS * VCODES];  // coarse scores

// ---------------------------------------------------------------------------
__device__ __forceinline__ uint32_t smem_u32(const void* p) {
    uint32_t a;
    asm("{ .reg .u64 t; cvta.to.shared.u64 t, %1; cvt.u32.u64 %0, t; }" : "=r"(a) : "l"(p));
    return a;
}
__device__ __forceinline__ void cp16(uint32_t dst, const void* src) {
    asm volatile("cp.async.cg.shared.global [%0], [%1], 16;" :: "r"(dst), "l"(src) : "memory");
}
__device__ __forceinline__ void ldm4(uint32_t* r, uint32_t addr) {
    asm volatile("ldmatrix.sync.aligned.m8n8.x4.shared.b16 {%0,%1,%2,%3}, [%4];"
                 : "=r"(r[0]), "=r"(r[1]), "=r"(r[2]), "=r"(r[3]) : "r"(addr));
}
__device__ __forceinline__ void imma16832(int* c, const uint32_t* a, const uint32_t* b) {
    asm volatile(
        "mma.sync.aligned.m16n8k32.row.col.s32.s8.s8.s32 "
        "{%0,%1,%2,%3}, {%4,%5,%6,%7}, {%8,%9}, {%0,%1,%2,%3};"
        : "+r"(c[0]), "+r"(c[1]), "+r"(c[2]), "+r"(c[3])
        : "r"(a[0]), "r"(a[1]), "r"(a[2]), "r"(a[3]), "r"(b[0]), "r"(b[1]));
}
__device__ __forceinline__ void st_cs32(void* p, uint32_t v) {
    asm volatile("st.global.cs.b32 [%0], %1;" :: "l"(p), "r"(v) : "memory");
}
__device__ __forceinline__ uint32_t pack4(float a, float b, float c, float d, float inv) {
    int q0 = max(-127, min(127, __float2int_rn(a * inv)));
    int q1 = max(-127, min(127, __float2int_rn(b * inv)));
    int q2 = max(-127, min(127, __float2int_rn(c * inv)));
    int q3 = max(-127, min(127, __float2int_rn(d * inv)));
    return (uint32_t)(q0 & 255) | ((uint32_t)(q1 & 255) << 8) |
           ((uint32_t)(q2 & 255) << 16) | ((uint32_t)(q3 & 255) << 24);
}

// ---------------------------------------------------------------------------
__global__ void k_zero() {
    int i = blockIdx.x * 256 + threadIdx.x;       // grid covers 2097152
    if (i < VCODES * DDIM) g_encsum[i] = 0.0f;
    if (i < MROWS)  g_best[i] = 0ull;
    if (i < VCODES) g_counts[i] = 0.0f;
    if (i == 0) { g_sumN = 0.0f; g_qd = 0.0f; }
}

// x (b, D=k, s) -> int8 rows g_axs8[r=b*4096+s][k] + per-row scale
__global__ void k_prep_x(const float* __restrict__ x) {
    __shared__ float t[32][257];
    int s0 = blockIdx.x * 32, b = blockIdx.y;
    int tx = threadIdx.x, ty = threadIdx.y;       // (32, 8)
#pragma unroll
    for (int it = 0; it < 32; ++it) {
        int k = it * 8 + ty;
        t[tx][k] = x[(size_t)b * 1048576 + (size_t)k * SPAT + s0 + tx];
    }
    __syncthreads();
#pragma unroll
    for (int rr = 0; rr < 4; ++rr) {
        int row = ty * 4 + rr;
        float m = 0.0f;
#pragma unroll
        for (int q = 0; q < 8; ++q) m = fmaxf(m, fabsf(t[row][tx + q * 32]));
#pragma unroll
        for (int o = 16; o; o >>= 1) m = fmaxf(m, __shfl_xor_sync(0xFFFFFFFFu, m, o));
        float scale = (m > 0.0f) ? (m * (1.0f / 127.0f)) : 1.0f;
        float inv = 1.0f / scale;
        int rg = b * SPAT + s0 + row;
        const float* tr = t[row];
        int k0 = tx * 8;
        uint2 pk;
        pk.x = pack4(tr[k0 + 0], tr[k0 + 1], tr[k0 + 2], tr[k0 + 3], inv);
        pk.y = pack4(tr[k0 + 4], tr[k0 + 5], tr[k0 + 6], tr[k0 + 7], inv);
        *reinterpret_cast<uint2*>(&g_axs8[(size_t)rg * DDIM + k0]) = pk;
        if (tx == 0) g_sx[rg] = scale;
    }
}

// weight -> int8 + scale; wsq per code; sum(N). One warp per code.
__global__ void k_prep_w(const float* __restrict__ w, const float* __restrict__ N) {
    int gid  = blockIdx.x * 256 + threadIdx.x;
    int v = gid >> 5, lane = gid & 31;
    const float* row = w + (size_t)v * DDIM;
    float4 f0 = *reinterpret_cast<const float4*>(row + lane * 8);
    float4 f1 = *reinterpret_cast<const float4*>(row + lane * 8 + 4);
    float s = f0.x*f0.x + f0.y*f0.y + f0.z*f0.z + f0.w*f0.w
            + f1.x*f1.x + f1.y*f1.y + f1.z*f1.z + f1.w*f1.w;
    float m = fmaxf(fmaxf(fmaxf(fabsf(f0.x), fabsf(f0.y)), fmaxf(fabsf(f0.z), fabsf(f0.w))),
                    fmaxf(fmaxf(fabsf(f1.x), fabsf(f1.y)), fmaxf(fabsf(f1.z), fabsf(f1.w))));
#pragma unroll
    for (int o = 16; o; o >>= 1) {
        s += __shfl_xor_sync(0xFFFFFFFFu, s, o);
        m = fmaxf(m, __shfl_xor_sync(0xFFFFFFFFu, m, o));
    }
    float scale = (m > 0.0f) ? (m * (1.0f / 127.0f)) : 1.0f;
    float inv = 1.0f / scale;
    uint2 pk;
    pk.x = pack4(f0.x, f0.y, f0.z, f0.w, inv);
    pk.y = pack4(f1.x, f1.y, f1.z, f1.w, inv);
    *reinterpret_cast<uint2*>(&g_wxs8[(size_t)v * DDIM + lane * 8]) = pk;
    if (lane == 0) {
        g_wsq[v] = s;
        g_sw[v] = scale;
        atomicAdd(&g_sumN, N[v]);
    }
}

// ---------------------------------------------------------------------------
// int8 IMMA GEMM: CTA 128x128, 8 warps of 64x32. Whole K=256B tile pair in
// one 64KB smem shot -> ONE barrier, zero mid-loop syncs. 16B-chunk swizzle
// c ^= row&7 keeps ldmatrix conflict-free (256B rows).
#define SMEM_DYN 65536

__global__ __launch_bounds__(256, 2) void k_gemm() {
    extern __shared__ __align__(16) char sm[];
    const int tid = threadIdx.x;
    const int lane = tid & 31, wid = tid >> 5;
    const int wm = wid & 1, wn = wid >> 1;        // warp tile 64m x 32n
    const int jbase = blockIdx.x * 128;
    const int rbase = blockIdx.y * 128;
    const uint32_t smb = smem_u32(sm);

    const int sel = lane >> 3, rin = lane & 7;

    // fragment row bases + swizzle (A: rows 0..127 at 0; B: at 32768)
    uint32_t baseA[4]; int vA[4];
#pragma unroll
    for (int i = 0; i < 4; ++i) {
        int row = wm * 64 + i * 16 + rin + ((sel & 1) << 3);
        baseA[i] = (uint32_t)(row * 256);
        vA[i] = row & 7;
    }
    const int hA = sel >> 1;
    uint32_t baseB[2]; int vB[2];
#pragma unroll
    for (int p = 0; p < 2; ++p) {
        int row = wn * 32 + p * 16 + rin + ((sel >> 1) << 3);
        baseB[p] = (uint32_t)(32768 + row * 256);
        vB[p] = row & 7;
    }
    const int hB = sel & 1;

    // one-shot load: 4096 x 16B chunks, 16 per thread
#pragma unroll
    for (int e = 0; e < 16; ++e) {
        int idx = tid + e * 256;                  // 0..4095
        int row = (idx >> 4) & 127, c = idx & 15;
        uint32_t sw = (uint32_t)((c ^ (row & 7)) << 4);
        if (idx < 2048)
            cp16(smb + row * 256 + sw, g_axs8 + (size_t)(rbase + row) * DDIM + c * 16);
        else
            cp16(smb + 32768 + row * 256 + sw, g_wxs8 + (size_t)(jbase + row) * DDIM + c * 16);
    }
    asm volatile("cp.async.commit_group;" ::: "memory");
    asm volatile("cp.async.wait_group 0;" ::: "memory");
    __syncthreads();

    int acc[4][4][4];
#pragma unroll
    for (int i = 0; i < 4; ++i)
#pragma unroll
        for (int j = 0; j < 4; ++j)
#pragma unroll
            for (int q = 0; q < 4; ++q) acc[i][j][q] = 0;

#pragma unroll
    for (int ks = 0; ks < 8; ++ks) {              // 8 x K32 groups
        uint32_t a[4][4], bf[4][2];
#pragma unroll
        for (int i = 0; i < 4; ++i)
            ldm4(a[i], smb + baseA[i] + (((2 * ks + hA) ^ vA[i]) << 4));
#pragma unroll
        for (int p = 0; p < 2; ++p) {
            uint32_t r4[4];
            ldm4(r4, smb + baseB[p] + (((2 * ks + hB) ^ vB[p]) << 4));
            bf[2 * p][0] = r4[0]; bf[2 * p][1] = r4[1];
            bf[2 * p + 1][0] = r4[2]; bf[2 * p + 1][1] = r4[3];
        }
#pragma unroll
        for (int i = 0; i < 4; ++i)
#pragma unroll
            for (int j = 0; j < 4; ++j)
                imma16832(acc[i][j], a[i], bf[j]);
    }

    // epilogue: score = acc*sx*sw - 0.5*wsq; store bf16 (streaming); argmax
    const int lq = lane >> 2, lr = lane & 3;
    float bv[8]; int bj[8]; float sxs[8];
#pragma unroll
    for (int s = 0; s < 8; ++s) {
        bv[s] = -3.4e38f; bj[s] = 0;
        int grow = rbase + wm * 64 + (s >> 1) * 16 + lq + (s & 1) * 8;
        sxs[s] = g_sx[grow];
    }

#pragma unroll
    for (int j = 0; j < 4; ++j) {
        int col = jbase + wn * 32 + j * 8 + lr * 2;
        float2 wq = *reinterpret_cast<const float2*>(&g_wsq[col]);
        float2 sw = *reinterpret_cast<const float2*>(&g_sw[col]);
#pragma unroll
        for (int i = 0; i < 4; ++i) {
#pragma unroll
            for (int h = 0; h < 2; ++h) {
                int slot = i * 2 + h;
                float s0 = __int2float_rn(acc[i][j][h * 2 + 0]) * (sxs[slot] * sw.x) - 0.5f * wq.x;
                float s1 = __int2float_rn(acc[i][j][h * 2 + 1]) * (sxs[slot] * sw.y) - 0.5f * wq.y;
                int grow = rbase + wm * 64 + i * 16 + lq + h * 8;
                __nv_bfloat162 pr = __floats2bfloat162_rn(s0, s1);
                st_cs32(&g_scores[(size_t)grow * VCODES + col],
                        *reinterpret_cast<uint32_t*>(&pr));
                if (s0 > bv[slot]) { bv[slot] = s0; bj[slot] = col; }
                if (s1 > bv[slot]) { bv[slot] = s1; bj[slot] = col + 1; }
            }
        }
    }
#pragma unroll
    for (int s = 0; s < 8; ++s) {
        unsigned u = __float_as_uint(bv[s]);
        u = (u & 0x80000000u) ? ~u : (u | 0x80000000u);
        unsigned long long key = ((unsigned long long)u << 32) |
                                 (unsigned)(0xFFFFFFFFu - (unsigned)bj[s]);
#pragma unroll
        for (int o = 1; o < 4; o <<= 1) {
            unsigned long long v = __shfl_xor_sync(0xFFFFFFFFu, key, o);
            if (v > key) key = v;
        }
        if (lr == 0) {
            int grow = rbase + wm * 64 + (s >> 1) * 16 + lq + (s & 1) * 8;
            atomicMax(&g_best[grow], key);
        }
    }
}

// ---------------------------------------------------------------------------
// Repair: per-row warp rescans bf16 scores (streaming loads), exact fp32
// recompute of candidates within MARGIN of the coarse winner.
__global__ void k_repair(const float* __restrict__ x, const float* __restrict__ w,
                         float* __restrict__ out) {
    int r = blockIdx.x * 8 + (threadIdx.x >> 5);
    int lane = threadIdx.x & 31;
    unsigned long long kk = g_best[r];
    unsigned u = (unsigned)(kk >> 32);
    unsigned bits = (u & 0x80000000u) ? (u & 0x7FFFFFFFu) : ~u;
    float thr = __uint_as_float(bits) - MARGIN;
    int b = r >> 12, s = r & 4095;
    const float* xb = x + (size_t)b * 1048576 + s;
    float bestv = -3.4e38f;
    int   bestj = 0;
    const uint4* rowp = reinterpret_cast<const uint4*>(g_scores + (size_t)r * VCODES);
#pragma unroll 1
    for (int it = 0; it < 32; ++it) {
        uint4 v = __ldcs(rowp + it * 32 + lane);
        unsigned m = 0;
        unsigned wds[4] = {v.x, v.y, v.z, v.w};
#pragma unroll
        for (int q = 0; q < 4; ++q) {
            __nv_bfloat162 h2 = *reinterpret_cast<__nv_bfloat162*>(&wds[q]);
            float2 f = __bfloat1622float2(h2);
            if (f.x >= thr) m |= 1u << (2 * q);
            if (f.y >= thr) m |= 1u << (2 * q + 1);
        }
        unsigned act = __ballot_sync(0xFFFFFFFFu, m != 0);
        while (act) {
            int src = __ffs(act) - 1; act &= act - 1;
            unsigned mm = __shfl_sync(0xFFFFFFFFu, m, src);
            while (mm) {
                int bit = __ffs(mm) - 1; mm &= mm - 1;
                int j = it * 256 + src * 8 + bit;
                const float* wr = w + (size_t)j * DDIM;
                float p = 0.0f;
#pragma unroll
                for (int q = 0; q < 8; ++q) {
                    int k = lane + q * 32;
                    p += xb[(size_t)k * SPAT] * wr[k];
                }
#pragma unroll
                for (int o = 16; o; o >>= 1) p += __shfl_xor_sync(0xFFFFFFFFu, p, o);
                float sc = p - 0.5f * g_wsq[j];
                if (sc > bestv) { bestv = sc; bestj = j; }   // ascending j -> first-idx tie-break
            }
        }
    }
    if (lane == 0) {
        g_idx[r] = bestj;
        out[O_IDX + r] = (float)bestj;
        atomicAdd(&g_counts[bestj], 1.0f);
    }
}

// ---------------------------------------------------------------------------
// quant write (coalesced over spatial), enc_sum atomics, quant_diff
__global__ void k_assign(const float* __restrict__ x, const float* __restrict__ w,
                         float* __restrict__ out) {
    __shared__ int sidx[128];
    __shared__ float red[8];
    int bi = blockIdx.x;
    int b = bi >> 5, s0 = (bi & 31) * 128;
    int tid = threadIdx.x, ts = tid & 127, dg = tid >> 7;
    if (tid < 128) sidx[tid] = g_idx[b * SPAT + s0 + tid];
    __syncthreads();
    int j = sidx[ts];
    const float* wr = w + (size_t)j * DDIM;
    float* er = g_encsum + (size_t)j * DDIM;
    size_t basex = (size_t)b * 1048576 + s0 + ts;
    float qd = 0.0f;
#pragma unroll 4
    for (int d = dg; d < 256; d += 2) {
        size_t off = basex + (size_t)d * SPAT;
        float xv = x[off];
        float wv = __ldg(wr + d);
        out[O_QUANT + off] = (wv - xv) + xv;
        float df = xv - wv;
        qd += df * df;
        atomicAdd(er + d, xv);
    }
#pragma unroll
    for (int o = 16; o; o >>= 1) qd += __shfl_xor_sync(0xFFFFFFFFu, qd, o);
    if ((tid & 31) == 0) red[tid >> 5] = qd;
    __syncthreads();
    if (tid == 0) {
        float t = 0.0f;
#pragma unroll
        for (int i = 0; i < 8; ++i) t += red[i];
        atomicAdd(&g_qd, t);
    }
}

// ---------------------------------------------------------------------------
__global__ void k_update(const float* __restrict__ N, const float* __restrict__ z_avg,
                         float* __restrict__ out) {
    int i = blockIdx.x * 256 + threadIdx.x;
    if (i >= VCODES * DDIM) return;
    int v = i >> 8, d = i & 255;
    float gamma = 0.99f, om = 0.01f, eps = 1e-7f;
    float n  = gamma * g_sumN + om * (float)MROWS;
    float nN = gamma * N[v] + om * g_counts[v];
    float wgt = (nN + eps) / (n + (float)VCODES * eps) * n;
    float za = gamma * z_avg[i] + om * g_encsum[i];
    out[O_ZAVG + i] = za;
    out[O_NEWW + i] = za / wgt;
    if (d == 0) out[O_NEWN + v] = nN;
    if (i == 0) out[O_QD] = g_qd * (1.0f / 8388608.0f);
}

// ---------------------------------------------------------------------------
extern "C" void kernel_launch(void* const* d_in, const int* in_sizes, int n_in,
                              void* d_out, int out_size) {
    const float* x    = (const float*)d_in[0];
    const float* w    = (const float*)d_in[1];
    const float* N    = (const float*)d_in[2];
    const float* zavg = (const float*)d_in[3];
    float* out = (float*)d_out;

    cudaFuncSetAttribute(k_gemm, cudaFuncAttributeMaxDynamicSharedMemorySize, SMEM_DYN);

    k_zero<<<8192, 256>>>();
    k_prep_x<<<dim3(128, 8), dim3(32, 8)>>>(x);
    k_prep_w<<<1024, 256>>>(w, N);
    k_gemm<<<dim3(VCODES / 128, MROWS / 128), 256, SMEM_DYN>>>();
    k_repair<<<MROWS / 8, 256>>>(x, w, out);
    k_assign<<<256, 256>>>(x, w, out);
    k_update<<<VCODES * DDIM / 256, 256>>>(N, zavg, out);
}

// round 10
// speedup vs baseline: 1.5691x; 1.5691x over previous
#include <cuda_runtime.h>
#include <cuda_bf16.h>
#include <cstdint>

// Problem constants
#define VCODES 8192
#define DDIM   256
#define MROWS  32768      // 8 * 16*16*16
#define SPAT   4096       // 16*16*16

// Output layout (concatenated f32)
#define O_QUANT 0ul
#define O_IDX   8388608ul
#define O_QD    8421376ul
#define O_NEWN  8421377ul
#define O_ZAVG  8429569ul
#define O_NEWW  10526721ul

#define MARGIN 3.0f

// ---------------------------------------------------------------------------
// Scratch (device globals; no allocations allowed)
__device__ unsigned long long g_best[MROWS];
__device__ int   g_idx[MROWS];
__device__ float g_counts[VCODES];
__device__ float g_encsum[VCODES * DDIM];
__device__ float g_wsq[VCODES];
__device__ float g_sumN;
__device__ float g_qd;
__device__ __nv_bfloat16 g_abf[MROWS * DDIM];    // flat x, bf16
__device__ __nv_bfloat16 g_wbf[VCODES * DDIM];   // weight, bf16
__device__ __nv_bfloat16 g_scores[(size_t)MROWS * VCODES];  // coarse scores

// ---------------------------------------------------------------------------
__device__ __forceinline__ uint32_t smem_u32(const void* p) {
    uint32_t a;
    asm("{ .reg .u64 t; cvta.to.shared.u64 t, %1; cvt.u32.u64 %0, t; }" : "=r"(a) : "l"(p));
    return a;
}
__device__ __forceinline__ void cp16(uint32_t dst, const void* src) {
    asm volatile("cp.async.cg.shared.global [%0], [%1], 16;" :: "r"(dst), "l"(src) : "memory");
}
__device__ __forceinline__ void ldm4(uint32_t* r, uint32_t addr) {
    asm volatile("ldmatrix.sync.aligned.m8n8.x4.shared.b16 {%0,%1,%2,%3}, [%4];"
                 : "=r"(r[0]), "=r"(r[1]), "=r"(r[2]), "=r"(r[3]) : "r"(addr));
}
__device__ __forceinline__ void mma16816(float* c, const uint32_t* a, const uint32_t* b) {
    asm volatile(
        "mma.sync.aligned.m16n8k16.row.col.f32.bf16.bf16.f32 "
        "{%0,%1,%2,%3}, {%4,%5,%6,%7}, {%8,%9}, {%0,%1,%2,%3};"
        : "+f"(c[0]), "+f"(c[1]), "+f"(c[2]), "+f"(c[3])
        : "r"(a[0]), "r"(a[1]), "r"(a[2]), "r"(a[3]), "r"(b[0]), "r"(b[1]));
}
__device__ __forceinline__ void st_cs32(void* p, uint32_t v) {
    asm volatile("st.global.cs.b32 [%0], %1;" :: "l"(p), "r"(v) : "memory");
}

// ---------------------------------------------------------------------------
__global__ void k_zero() {
    int i = blockIdx.x * 256 + threadIdx.x;       // grid covers 2097152
    if (i < VCODES * DDIM) g_encsum[i] = 0.0f;
    if (i < MROWS)  g_best[i] = 0ull;
    if (i < VCODES) g_counts[i] = 0.0f;
    if (i == 0) { g_sumN = 0.0f; g_qd = 0.0f; }
}

// x (b, D=k, s) -> g_abf[r=b*4096+s][k] bf16
__global__ void k_prep_x(const float* __restrict__ x) {
    __shared__ float t[32][33];
    int k0 = blockIdx.x * 32, s0 = blockIdx.y * 32, b = blockIdx.z;
    int tx = threadIdx.x, ty = threadIdx.y;       // (32, 8)
#pragma unroll
    for (int i = 0; i < 4; ++i)
        t[ty + i * 8][tx] = x[(size_t)b * 1048576 + (size_t)(k0 + ty + i * 8) * SPAT + s0 + tx];
    __syncthreads();
#pragma unroll
    for (int i = 0; i < 4; ++i) {
        int r = b * SPAT + s0 + ty + i * 8;
        g_abf[(size_t)r * DDIM + k0 + tx] = __float2bfloat16(t[tx][ty + i * 8]);
    }
}

// weight -> bf16; wsq per code; sum(N)
__global__ void k_prep_w(const float* __restrict__ w, const float* __restrict__ N) {
    int gid  = blockIdx.x * 256 + threadIdx.x;
    int v = gid >> 5, lane = gid & 31;
    const float* row = w + (size_t)v * DDIM;
    float s = 0.0f;
#pragma unroll
    for (int t = lane; t < DDIM; t += 32) {
        float a = row[t];
        s += a * a;
        g_wbf[(size_t)v * DDIM + t] = __float2bfloat16(a);
    }
#pragma unroll
    for (int o = 16; o; o >>= 1) s += __shfl_xor_sync(0xFFFFFFFFu, s, o);
    if (lane == 0) {
        g_wsq[v] = s;
        atomicAdd(&g_sumN, N[v]);
    }
}

// ---------------------------------------------------------------------------
// bf16 HMMA GEMM in the R9 (saturating) structure: CTA 128x128, 8 warps of
// 64x32. K=256 split into 2 halves; per half one 64KB one-shot load + ONE
// barrier, then an unbroken run of 8 x (6 ldsm + 16 mma). 2 CTAs/SM overlap
// each other's load phases. 256B rows, 16B-chunk swizzle c ^= row&7.
#define SMEM_DYN 65536

__global__ __launch_bounds__(256, 2) void k_gemm() {
    extern __shared__ __align__(16) char sm[];
    const int tid = threadIdx.x;
    const int lane = tid & 31, wid = tid >> 5;
    const int wm = wid & 1, wn = wid >> 1;        // warp tile 64m x 32n
    const int jbase = blockIdx.x * 128;
    const int rbase = blockIdx.y * 128;
    const uint32_t smb = smem_u32(sm);

    const int sel = lane >> 3, rin = lane & 7;

    // fragment row bases + swizzle (A rows at 0, B rows at 32768; 256B rows)
    uint32_t baseA[4]; int vA[4];
#pragma unroll
    for (int i = 0; i < 4; ++i) {
        int row = wm * 64 + i * 16 + rin + ((sel & 1) << 3);
        baseA[i] = (uint32_t)(row * 256);
        vA[i] = row & 7;
    }
    const int hA = sel >> 1;
    uint32_t baseB[2]; int vB[2];
#pragma unroll
    for (int p = 0; p < 2; ++p) {
        int row = wn * 32 + p * 16 + rin + ((sel >> 1) << 3);
        baseB[p] = (uint32_t)(32768 + row * 256);
        vB[p] = row & 7;
    }
    const int hB = sel & 1;

    float acc[4][4][4];
#pragma unroll
    for (int i = 0; i < 4; ++i)
#pragma unroll
        for (int j = 0; j < 4; ++j)
#pragma unroll
            for (int q = 0; q < 4; ++q) acc[i][j][q] = 0.0f;

#pragma unroll
    for (int r = 0; r < 2; ++r) {
        // one-shot load of this K-half: 4096 x 16B chunks, 16 per thread
#pragma unroll
        for (int e = 0; e < 16; ++e) {
            int idx = tid + e * 256;              // 0..4095
            int row = (idx >> 4) & 127, c = idx & 15;
            uint32_t sw = (uint32_t)((c ^ (row & 7)) << 4);
            if (idx < 2048)
                cp16(smb + row * 256 + sw,
                     g_abf + (size_t)(rbase + row) * DDIM + r * 128 + c * 8);
            else
                cp16(smb + 32768 + row * 256 + sw,
                     g_wbf + (size_t)(jbase + row) * DDIM + r * 128 + c * 8);
        }
        asm volatile("cp.async.commit_group;" ::: "memory");
        asm volatile("cp.async.wait_group 0;" ::: "memory");
        __syncthreads();

        // unbroken MMA run over this half (8 x K16)
#pragma unroll
        for (int ks = 0; ks < 8; ++ks) {
            uint32_t a[4][4], bf[4][2];
#pragma unroll
            for (int i = 0; i < 4; ++i)
                ldm4(a[i], smb + baseA[i] + (((2 * ks + hA) ^ vA[i]) << 4));
#pragma unroll
            for (int p = 0; p < 2; ++p) {
                uint32_t r4[4];
                ldm4(r4, smb + baseB[p] + (((2 * ks + hB) ^ vB[p]) << 4));
                bf[2 * p][0] = r4[0]; bf[2 * p][1] = r4[1];
                bf[2 * p + 1][0] = r4[2]; bf[2 * p + 1][1] = r4[3];
            }
#pragma unroll
            for (int i = 0; i < 4; ++i)
#pragma unroll
                for (int j = 0; j < 4; ++j)
                    mma16816(acc[i][j], a[i], bf[j]);
        }
        if (r == 0) __syncthreads();              // protect buffer before reload
    }

    // epilogue: scores = acc - 0.5*wsq; store bf16 (streaming); per-row argmax
    const int lq = lane >> 2, lr = lane & 3;
    float bv[8]; int bj[8];
#pragma unroll
    for (int s = 0; s < 8; ++s) { bv[s] = -3.4e38f; bj[s] = 0; }

#pragma unroll
    for (int j = 0; j < 4; ++j) {
        int col = jbase + wn * 32 + j * 8 + lr * 2;
        float2 wq = *reinterpret_cast<const float2*>(&g_wsq[col]);
#pragma unroll
        for (int i = 0; i < 4; ++i) {
#pragma unroll
            for (int h = 0; h < 2; ++h) {
                float s0 = acc[i][j][h * 2 + 0] - 0.5f * wq.x;
                float s1 = acc[i][j][h * 2 + 1] - 0.5f * wq.y;
                int grow = rbase + wm * 64 + i * 16 + lq + h * 8;
                __nv_bfloat162 pr = __floats2bfloat162_rn(s0, s1);
                st_cs32(&g_scores[(size_t)grow * VCODES + col],
                        *reinterpret_cast<uint32_t*>(&pr));
                int slot = i * 2 + h;
                if (s0 > bv[slot]) { bv[slot] = s0; bj[slot] = col; }
                if (s1 > bv[slot]) { bv[slot] = s1; bj[slot] = col + 1; }
            }
        }
    }
#pragma unroll
    for (int s = 0; s < 8; ++s) {
        unsigned u = __float_as_uint(bv[s]);
        u = (u & 0x80000000u) ? ~u : (u | 0x80000000u);
        unsigned long long key = ((unsigned long long)u << 32) |
                                 (unsigned)(0xFFFFFFFFu - (unsigned)bj[s]);
#pragma unroll
        for (int o = 1; o < 4; o <<= 1) {
            unsigned long long v = __shfl_xor_sync(0xFFFFFFFFu, key, o);
            if (v > key) key = v;
        }
        if (lr == 0) {
            int grow = rbase + wm * 64 + (s >> 1) * 16 + lq + (s & 1) * 8;
            atomicMax(&g_best[grow], key);
        }
    }
}

// ---------------------------------------------------------------------------
// Repair: per-row warp rescans bf16 scores (streaming loads), exact fp32
// recompute of candidates within MARGIN of the coarse winner.
__global__ void k_repair(const float* __restrict__ x, const float* __restrict__ w,
                         float* __restrict__ out) {
    int r = blockIdx.x * 8 + (threadIdx.x >> 5);
    int lane = threadIdx.x & 31;
    unsigned long long kk = g_best[r];
    unsigned u = (unsigned)(kk >> 32);
    unsigned bits = (u & 0x80000000u) ? (u & 0x7FFFFFFFu) : ~u;
    float thr = __uint_as_float(bits) - MARGIN;
    int b = r >> 12, s = r & 4095;
    const float* xb = x + (size_t)b * 1048576 + s;
    float bestv = -3.4e38f;
    int   bestj = 0;
    const uint4* rowp = reinterpret_cast<const uint4*>(g_scores + (size_t)r * VCODES);
#pragma unroll 1
    for (int it = 0; it < 32; ++it) {
        uint4 v = __ldcs(rowp + it * 32 + lane);
        unsigned m = 0;
        unsigned wds[4] = {v.x, v.y, v.z, v.w};
#pragma unroll
        for (int q = 0; q < 4; ++q) {
            __nv_bfloat162 h2 = *reinterpret_cast<__nv_bfloat162*>(&wds[q]);
            float2 f = __bfloat1622float2(h2);
            if (f.x >= thr) m |= 1u << (2 * q);
            if (f.y >= thr) m |= 1u << (2 * q + 1);
        }
        unsigned act = __ballot_sync(0xFFFFFFFFu, m != 0);
        while (act) {
            int src = __ffs(act) - 1; act &= act - 1;
            unsigned mm = __shfl_sync(0xFFFFFFFFu, m, src);
            while (mm) {
                int bit = __ffs(mm) - 1; mm &= mm - 1;
                int j = it * 256 + src * 8 + bit;
                const float* wr = w + (size_t)j * DDIM;
                float p = 0.0f;
#pragma unroll
                for (int q = 0; q < 8; ++q) {
                    int k = lane + q * 32;
                    p += xb[(size_t)k * SPAT] * wr[k];
                }
#pragma unroll
                for (int o = 16; o; o >>= 1) p += __shfl_xor_sync(0xFFFFFFFFu, p, o);
                float sc = p - 0.5f * g_wsq[j];
                if (sc > bestv) { bestv = sc; bestj = j; }   // ascending j -> first-idx tie-break
            }
        }
    }
    if (lane == 0) {
        g_idx[r] = bestj;
        out[O_IDX + r] = (float)bestj;
        atomicAdd(&g_counts[bestj], 1.0f);
    }
}

// ---------------------------------------------------------------------------
// quant write (coalesced over spatial), enc_sum atomics, quant_diff
__global__ void k_assign(const float* __restrict__ x, const float* __restrict__ w,
                         float* __restrict__ out) {
    __shared__ int sidx[128];
    __shared__ float red[8];
    int bi = blockIdx.x;
    int b = bi >> 5, s0 = (bi & 31) * 128;
    int tid = threadIdx.x, ts = tid & 127, dg = tid >> 7;
    if (tid < 128) sidx[tid] = g_idx[b * SPAT + s0 + tid];
    __syncthreads();
    int j = sidx[ts];
    const float* wr = w + (size_t)j * DDIM;
    float* er = g_encsum + (size_t)j * DDIM;
    size_t basex = (size_t)b * 1048576 + s0 + ts;
    float qd = 0.0f;
#pragma unroll 4
    for (int d = dg; d < 256; d += 2) {
        size_t off = basex + (size_t)d * SPAT;
        float xv = x[off];
        float wv = __ldg(wr + d);
        out[O_QUANT + off] = (wv - xv) + xv;
        float df = xv - wv;
        qd += df * df;
        atomicAdd(er + d, xv);
    }
#pragma unroll
    for (int o = 16; o; o >>= 1) qd += __shfl_xor_sync(0xFFFFFFFFu, qd, o);
    if ((tid & 31) == 0) red[tid >> 5] = qd;
    __syncthreads();
    if (tid == 0) {
        float t = 0.0f;
#pragma unroll
        for (int i = 0; i < 8; ++i) t += red[i];
        atomicAdd(&g_qd, t);
    }
}

// ---------------------------------------------------------------------------
__global__ void k_update(const float* __restrict__ N, const float* __restrict__ z_avg,
                         float* __restrict__ out) {
    int i = blockIdx.x * 256 + threadIdx.x;
    if (i >= VCODES * DDIM) return;
    int v = i >> 8, d = i & 255;
    float gamma = 0.99f, om = 0.01f, eps = 1e-7f;
    float n  = gamma * g_sumN + om * (float)MROWS;
    float nN = gamma * N[v] + om * g_counts[v];
    float wgt = (nN + eps) / (n + (float)VCODES * eps) * n;
    float za = gamma * z_avg[i] + om * g_encsum[i];
    out[O_ZAVG + i] = za;
    out[O_NEWW + i] = za / wgt;
    if (d == 0) out[O_NEWN + v] = nN;
    if (i == 0) out[O_QD] = g_qd * (1.0f / 8388608.0f);
}

// ---------------------------------------------------------------------------
extern "C" void kernel_launch(void* const* d_in, const int* in_sizes, int n_in,
                              void* d_out, int out_size) {
    const float* x    = (const float*)d_in[0];
    const float* w    = (const float*)d_in[1];
    const float* N    = (const float*)d_in[2];
    const float* zavg = (const float*)d_in[3];
    float* out = (float*)d_out;

    cudaFuncSetAttribute(k_gemm, cudaFuncAttributeMaxDynamicSharedMemorySize, SMEM_DYN);

    k_zero<<<8192, 256>>>();
    k_prep_x<<<dim3(8, 128, 8), dim3(32, 8)>>>(x);
    k_prep_w<<<1024, 256>>>(w, N);
    k_gemm<<<dim3(VCODES / 128, MROWS / 128), 256, SMEM_DYN>>>();
    k_repair<<<MROWS / 8, 256>>>(x, w, out);
    k_assign<<<256, 256>>>(x, w, out);
    k_update<<<VCODES * DDIM / 256, 256>>>(N, zavg, out);
}